// round 15
// baseline (speedup 1.0000x reference)
#include <cuda_runtime.h>
#include <cuda_bf16.h>
#include <cstdint>

#define B_   64
#define T_   320
#define H_   256
#define D_   512
#define TB   (T_*B_)
#define SCAN_SMEM ((12*256 + 64*260 + 256)*4)
#define BUF_BYTES 98304
#define GEMM_DSMEM (2*BUF_BYTES + 1024)
#define S2E 2.885390081777927f   /* 2*log2(e) */

// ---------------- fp32 scratch ----------------
__device__ float g_cm  [(size_t)TB*D_];
__device__ float g_cwm [(size_t)TB*D_];
__device__ float g_gixf[(size_t)TB*3*H_];
__device__ float g_gixb[(size_t)TB*3*H_];
__device__ float g_Hbuf[2*2*B_*H_];     // [buf][dir][b][k]
__device__ unsigned g_cnt2[2];
__device__ unsigned g_gen2[2];

// ---------------- bf16 hi/lo planes ----------------
__device__ __nv_bfloat16 g_vhi [(size_t)TB*D_],   g_vlo [(size_t)TB*D_];
__device__ __nv_bfloat16 g_pghi[(size_t)TB*2*D_], g_pglo[(size_t)TB*2*D_];
__device__ __nv_bfloat16 g_gihi[(size_t)TB*2*D_], g_gilo[(size_t)TB*2*D_];
__device__ __nv_bfloat16 g_w1hi[D_*D_],     g_w1lo[D_*D_];
__device__ __nv_bfloat16 g_w2hi[D_*D_],     g_w2lo[D_*D_];
__device__ __nv_bfloat16 g_wghi[2*D_*2*D_], g_wglo[2*D_*2*D_];
__device__ __nv_bfloat16 g_wfhi[3*H_*2*D_], g_wflo[3*H_*2*D_];
__device__ __nv_bfloat16 g_wbhi[3*H_*2*D_], g_wblo[3*H_*2*D_];

// ---------------- math ----------------
__device__ __forceinline__ float ex2f(float x){ float r; asm("ex2.approx.f32 %0, %1;" : "=f"(r) : "f"(x)); return r; }
__device__ __forceinline__ float rcpf(float x){ float r; asm("rcp.approx.f32 %0, %1;" : "=f"(r) : "f"(x)); return r; }
__device__ __forceinline__ float tanh_acc(float x){
    x = fminf(15.f, fmaxf(-15.f, x));
    float e = ex2f(x * S2E);
    return (e - 1.f) * rcpf(e + 1.f);
}
__device__ __forceinline__ float sigm(float x){
    x = fminf(30.f, fmaxf(-30.f, x));
    return rcpf(1.f + ex2f(-x * 1.4426950408889634f));
}

// ---------------- packed f32x2 helpers ----------------
__device__ __forceinline__ uint64_t pk2(float a, float b){
    uint64_t r; asm("mov.b64 %0, {%1, %2};" : "=l"(r) : "f"(a), "f"(b)); return r;
}
__device__ __forceinline__ void upk2(uint64_t p, float& a, float& b){
    asm("mov.b64 {%0, %1}, %2;" : "=f"(a), "=f"(b) : "l"(p));
}
__device__ __forceinline__ uint64_t add2(uint64_t a, uint64_t b){
    uint64_t r; asm("add.rn.f32x2 %0, %1, %2;" : "=l"(r) : "l"(a), "l"(b)); return r;
}
__device__ __forceinline__ uint64_t mul2(uint64_t a, uint64_t b){
    uint64_t r; asm("mul.rn.f32x2 %0, %1, %2;" : "=l"(r) : "l"(a), "l"(b)); return r;
}
__device__ __forceinline__ uint64_t fma2(uint64_t a, uint64_t b, uint64_t c){
    uint64_t r; asm("fma.rn.f32x2 %0, %1, %2, %3;" : "=l"(r) : "l"(a), "l"(b), "l"(c)); return r;
}

__device__ __forceinline__ uint32_t smem_u32(const void* p) {
    uint32_t a;
    asm("{ .reg .u64 t; cvta.to.shared.u64 t, %1; cvt.u32.u64 %0, t; }" : "=r"(a) : "l"(p));
    return a;
}
__device__ __forceinline__ uint32_t swz(uint32_t o){ return o ^ ((o >> 3) & 0x70); }

__device__ __forceinline__ void ldm4(uint32_t* r, uint32_t addr){
    asm volatile("ldmatrix.sync.aligned.m8n8.x4.shared.b16 {%0,%1,%2,%3}, [%4];"
        : "=r"(r[0]), "=r"(r[1]), "=r"(r[2]), "=r"(r[3]) : "r"(addr));
}
__device__ __forceinline__ void mma16816(float* c, const uint32_t* a, const uint32_t* b){
    asm volatile("mma.sync.aligned.m16n8k16.row.col.f32.bf16.bf16.f32 "
        "{%0,%1,%2,%3}, {%4,%5,%6,%7}, {%8,%9}, {%0,%1,%2,%3};"
        : "+f"(c[0]), "+f"(c[1]), "+f"(c[2]), "+f"(c[3])
        : "r"(a[0]), "r"(a[1]), "r"(a[2]), "r"(a[3]), "r"(b[0]), "r"(b[1]));
}
__device__ __forceinline__ void cpa16(uint32_t dst, const void* src){
    asm volatile("cp.async.cg.shared.global [%0], [%1], 16;" :: "r"(dst), "l"(src));
}
#define CP_COMMIT() asm volatile("cp.async.commit_group;" ::: "memory")
#define CP_WAIT1()  asm volatile("cp.async.wait_group 1;" ::: "memory")
#define CP_WAIT0()  asm volatile("cp.async.wait_group 0;" ::: "memory")

// ---------------- merged fp32 -> (hi, lo) bf16 split ----------------
__device__ __forceinline__ void split_one(const float* in, __nv_bfloat16* hi,
                                          __nv_bfloat16* lo, int i)
{
    float4 f = ((const float4*)in)[i];
    __nv_bfloat16 hx = __float2bfloat16_rn(f.x), hy = __float2bfloat16_rn(f.y);
    __nv_bfloat16 hz = __float2bfloat16_rn(f.z), hw = __float2bfloat16_rn(f.w);
    __nv_bfloat162 p0, p1; uint2 u;
    p0.x = hx; p0.y = hy; p1.x = hz; p1.y = hw;
    u.x = *(uint32_t*)&p0; u.y = *(uint32_t*)&p1;
    ((uint2*)hi)[i] = u;
    p0.x = __float2bfloat16_rn(f.x - __bfloat162float(hx));
    p0.y = __float2bfloat16_rn(f.y - __bfloat162float(hy));
    p1.x = __float2bfloat16_rn(f.z - __bfloat162float(hz));
    p1.y = __float2bfloat16_rn(f.w - __bfloat162float(hw));
    u.x = *(uint32_t*)&p0; u.y = *(uint32_t*)&p1;
    ((uint2*)lo)[i] = u;
}

__global__ void split6_kernel(
    const float* s0, const float* s1, const float* s2,
    const float* s3, const float* s4, const float* s5,
    __nv_bfloat16* h0, __nv_bfloat16* l0, __nv_bfloat16* h1, __nv_bfloat16* l1,
    __nv_bfloat16* h2, __nv_bfloat16* l2, __nv_bfloat16* h3, __nv_bfloat16* l3,
    __nv_bfloat16* h4, __nv_bfloat16* l4, __nv_bfloat16* h5, __nv_bfloat16* l5,
    int n0, int n1, int n2, int n3, int n4, int n5)
{
    int j = blockIdx.x * blockDim.x + threadIdx.x;
    if (j < n0){ split_one(s0, h0, l0, j); return; } j -= n0;
    if (j < n1){ split_one(s1, h1, l1, j); return; } j -= n1;
    if (j < n2){ split_one(s2, h2, l2, j); return; } j -= n2;
    if (j < n3){ split_one(s3, h3, l3, j); return; } j -= n3;
    if (j < n4){ split_one(s4, h4, l4, j); return; } j -= n4;
    if (j < n5){ split_one(s5, h5, l5, j); }
}

// ======== GEMM core ========
struct GemmCore {
    template<typename FA>
    __device__ __forceinline__ static void run(
        float (&acc)[4][8][4],
        const __nv_bfloat16* Ahi, const __nv_bfloat16* Alo,
        const __nv_bfloat16* Bhi, const __nv_bfloat16* Blo,
        int bm, int bnl, int K, int Ktiles,
        uint32_t tbase, int tid)
    {
        const int wid = tid >> 5, lane = tid & 31;
        const int wm = (wid & 1) * 64, wn = (wid >> 1) * 64;
        const uint32_t aoff0 = (uint32_t)(wm + (lane & 15)) * 128 + ((lane >> 4) << 4);
        const uint32_t boff0 = (uint32_t)(wn + (lane & 7) + ((lane >> 4) << 3)) * 128 + (((lane >> 3) & 1) << 4);

        auto issue = [&](int kt, int buf){
            const uint32_t bb = tbase + (uint32_t)buf * BUF_BYTES;
            const int kof = kt * 64;
            #pragma unroll
            for (int i = 0; i < 8; i++){
                int idx = tid + 256*i;
                int plane = idx >> 10, rem = idx & 1023, row = rem >> 3, ch = rem & 7;
                const __nv_bfloat16* src = (plane ? Alo : Ahi) + (size_t)(bm + row) * K + kof + ch*8;
                cpa16(bb + plane*16384u + swz((uint32_t)row*128 + ch*16), src);
            }
            #pragma unroll
            for (int i = 0; i < 16; i++){
                int idx = tid + 256*i;
                int plane = idx >> 11, rem = idx & 2047, row = rem >> 3, ch = rem & 7;
                const __nv_bfloat16* src = (plane ? Blo : Bhi) + (size_t)(bnl + row) * K + kof + ch*8;
                cpa16(bb + 32768u + plane*32768u + swz((uint32_t)row*128 + ch*16), src);
            }
        };

        issue(0, 0); CP_COMMIT();
        if (Ktiles > 1){ issue(1, 1); CP_COMMIT(); }

        for (int kt = 0; kt < Ktiles; kt++){
            if (kt + 1 < Ktiles) CP_WAIT1(); else CP_WAIT0();
            __syncthreads();

            const uint32_t ub = tbase + (uint32_t)(kt & 1) * BUF_BYTES;
            const uint32_t uAhi = ub, uAlo = ub + 16384, uBhi = ub + 32768, uBlo = ub + 65536;

            #pragma unroll
            for (int kk = 0; kk < 4; kk++){
                const uint32_t kb = kk * 32;
                uint32_t ah[4][4], al[4][4], bh[4][4], bl[4][4];
                #pragma unroll
                for (int mf = 0; mf < 4; mf++){
                    uint32_t off = swz(aoff0 + (uint32_t)mf*2048 + kb);
                    ldm4(ah[mf], uAhi + off);
                    ldm4(al[mf], uAlo + off);
                }
                #pragma unroll
                for (int nf2 = 0; nf2 < 4; nf2++){
                    uint32_t off = swz(boff0 + (uint32_t)nf2*2048 + kb);
                    ldm4(bh[nf2], uBhi + off);
                    ldm4(bl[nf2], uBlo + off);
                }
                #pragma unroll
                for (int pass = 0; pass < 3; pass++){
                    #pragma unroll
                    for (int mf = 0; mf < 4; mf++){
                        #pragma unroll
                        for (int nf = 0; nf < 8; nf++){
                            const uint32_t* ap = (pass == 2) ? al[mf] : ah[mf];
                            const uint32_t* bp = (pass == 1) ? &bl[nf >> 1][(nf & 1) * 2]
                                                             : &bh[nf >> 1][(nf & 1) * 2];
                            mma16816(acc[mf][nf], ap, bp);
                        }
                    }
                }
            }
            if (kt + 2 < Ktiles){
                __syncthreads();
                issue(kt + 2, kt & 1);
                CP_COMMIT();
            }
        }
    }
};

// ---------------- dual-output GEMM ----------------
__global__ __launch_bounds__(256, 1)
void tgemm_dual_kernel(const __nv_bfloat16* __restrict__ Ahi, const __nv_bfloat16* __restrict__ Alo,
                       const __nv_bfloat16* __restrict__ B1hi, const __nv_bfloat16* __restrict__ B1lo,
                       const __nv_bfloat16* __restrict__ B2hi, const __nv_bfloat16* __restrict__ B2lo,
                       const float* __restrict__ bias1, const float* __restrict__ bias2,
                       float* __restrict__ C1, float* __restrict__ C2,
                       int N1, int N2, int K, int Ktiles, float scl)
{
    extern __shared__ char dsm[];
    const int tid = threadIdx.x, wid = tid >> 5, lane = tid & 31;
    const int bm = blockIdx.y * 128, bn = blockIdx.x * 256;
    const int wm = (wid & 1) * 64, wn = (wid >> 1) * 64;
    uint32_t sbase = smem_u32(dsm);
    uint32_t tbase = (sbase + 1023u) & ~1023u;

    const bool second = (bn >= N1);
    const int bnl = second ? bn - N1 : bn;
    const __nv_bfloat16* Bhi = second ? B2hi : B1hi;
    const __nv_bfloat16* Blo = second ? B2lo : B1lo;
    const float* bias = second ? bias2 : bias1;
    float* C = second ? C2 : C1;
    const int Nout = second ? N2 : N1;

    float acc[4][8][4];
    #pragma unroll
    for (int i = 0; i < 4; i++)
        #pragma unroll
        for (int j = 0; j < 8; j++)
            #pragma unroll
            for (int q = 0; q < 4; q++) acc[i][j][q] = 0.f;

    GemmCore::run<int>(acc, Ahi, Alo, Bhi, Blo, bm, bnl, K, Ktiles, tbase, tid);

    #pragma unroll
    for (int mf = 0; mf < 4; mf++){
        const int row = bm + wm + mf*16 + (lane >> 2);
        #pragma unroll
        for (int nf = 0; nf < 8; nf++){
            const int col = bnl + wn + nf*8 + (lane & 3)*2;
            float2 bs = *(const float2*)&bias[col];
            float2 o0, o1;
            o0.x = (acc[mf][nf][0] + bs.x) * scl;  o0.y = (acc[mf][nf][1] + bs.y) * scl;
            o1.x = (acc[mf][nf][2] + bs.x) * scl;  o1.y = (acc[mf][nf][3] + bs.y) * scl;
            *(float2*)&C[(size_t)row * Nout + col]     = o0;
            *(float2*)&C[(size_t)(row+8) * Nout + col] = o1;
        }
    }
}

// ---------------- gate GEMM ----------------
__global__ __launch_bounds__(256, 1)
void tgemm_gate_kernel(const __nv_bfloat16* __restrict__ Ahi, const __nv_bfloat16* __restrict__ Alo,
                       const __nv_bfloat16* __restrict__ Bhi, const __nv_bfloat16* __restrict__ Blo,
                       const float* __restrict__ bias,
                       __nv_bfloat16* __restrict__ Chi, __nv_bfloat16* __restrict__ Clo,
                       int N, int K, int Ktiles)
{
    extern __shared__ char dsm[];
    const int tid = threadIdx.x, wid = tid >> 5, lane = tid & 31;
    const int bm = blockIdx.y * 128, bn = blockIdx.x * 256;
    const int wm = (wid & 1) * 64, wn = (wid >> 1) * 64;
    uint32_t sbase = smem_u32(dsm);
    uint32_t tbase = (sbase + 1023u) & ~1023u;

    float acc[4][8][4];
    #pragma unroll
    for (int i = 0; i < 4; i++)
        #pragma unroll
        for (int j = 0; j < 8; j++)
            #pragma unroll
            for (int q = 0; q < 4; q++) acc[i][j][q] = 0.f;

    GemmCore::run<int>(acc, Ahi, Alo, Bhi, Blo, bm, bn, K, Ktiles, tbase, tid);

    #pragma unroll
    for (int mf = 0; mf < 4; mf++){
        const int row = bm + wm + mf*16 + (lane >> 2);
        #pragma unroll
        for (int nf = 0; nf < 8; nf++){
            const int col = bn + wn + nf*8 + (lane & 3)*2;
            float2 bs = *(const float2*)&bias[col];
            float2 o0, o1;
            o0.x = acc[mf][nf][0] + bs.x;  o0.y = acc[mf][nf][1] + bs.y;
            o1.x = acc[mf][nf][2] + bs.x;  o1.y = acc[mf][nf][3] + bs.y;
            __nv_bfloat162 h0 = *(const __nv_bfloat162*)&Ahi[(size_t)row*K + col];
            __nv_bfloat162 l0 = *(const __nv_bfloat162*)&Alo[(size_t)row*K + col];
            __nv_bfloat162 h1 = *(const __nv_bfloat162*)&Ahi[(size_t)(row+8)*K + col];
            __nv_bfloat162 l1 = *(const __nv_bfloat162*)&Alo[(size_t)(row+8)*K + col];
            float g0x = (__bfloat162float(h0.x)+__bfloat162float(l0.x)) * sigm(o0.x);
            float g0y = (__bfloat162float(h0.y)+__bfloat162float(l0.y)) * sigm(o0.y);
            float g1x = (__bfloat162float(h1.x)+__bfloat162float(l1.x)) * sigm(o1.x);
            float g1y = (__bfloat162float(h1.y)+__bfloat162float(l1.y)) * sigm(o1.y);
            __nv_bfloat162 oh, ol;
            oh.x = __float2bfloat16_rn(g0x); oh.y = __float2bfloat16_rn(g0y);
            ol.x = __float2bfloat16_rn(g0x - __bfloat162float(oh.x));
            ol.y = __float2bfloat16_rn(g0y - __bfloat162float(oh.y));
            *(__nv_bfloat162*)&Chi[(size_t)row*N + col] = oh;
            *(__nv_bfloat162*)&Clo[(size_t)row*N + col] = ol;
            oh.x = __float2bfloat16_rn(g1x); oh.y = __float2bfloat16_rn(g1y);
            ol.x = __float2bfloat16_rn(g1x - __bfloat162float(oh.x));
            ol.y = __float2bfloat16_rn(g1y - __bfloat162float(oh.y));
            *(__nv_bfloat162*)&Chi[(size_t)(row+8)*N + col] = oh;
            *(__nv_bfloat162*)&Clo[(size_t)(row+8)*N + col] = ol;
        }
    }
}

// ---------------- fused attention ----------------
__global__ __launch_bounds__(256)
void attn_kernel(const float* __restrict__ v)
{
    __shared__ float s_sc[T_][10];
    __shared__ float s_rs[8];
    const int b = blockIdx.y;
    const int t0 = blockIdx.x << 3;
    const int tid = threadIdx.x, w = tid >> 5, lane = tid & 31;
    const int t = t0 + w;

    const float* vrow = v     + ((size_t)b*T_ + t)*D_;
    const float* mrow = g_cwm + ((size_t)b*T_ + t)*D_;
    float4 cw4[4], cwm4[4];
    #pragma unroll
    for (int i = 0; i < 4; i++){
        cw4[i]  = __ldg((const float4*)(vrow + lane*4 + 128*i));
        cwm4[i] = __ldg((const float4*)(mrow + lane*4 + 128*i));
    }
    {
        size_t ro = (size_t)(t*B_ + b)*(2*D_);
        #pragma unroll
        for (int i = 0; i < 4; i++){
            const float* f = (const float*)&cw4[i];
            __nv_bfloat162 ph0, ph1, pl0, pl1;
            ph0.x = __float2bfloat16_rn(f[0]); ph0.y = __float2bfloat16_rn(f[1]);
            ph1.x = __float2bfloat16_rn(f[2]); ph1.y = __float2bfloat16_rn(f[3]);
            pl0.x = __float2bfloat16_rn(f[0] - __bfloat162float(ph0.x));
            pl0.y = __float2bfloat16_rn(f[1] - __bfloat162float(ph0.y));
            pl1.x = __float2bfloat16_rn(f[2] - __bfloat162float(ph1.x));
            pl1.y = __float2bfloat16_rn(f[3] - __bfloat162float(ph1.y));
            uint2 uh, ul;
            uh.x = *(uint32_t*)&ph0; uh.y = *(uint32_t*)&ph1;
            ul.x = *(uint32_t*)&pl0; ul.y = *(uint32_t*)&pl1;
            *(uint2*)&g_pghi[ro + lane*4 + 128*i] = uh;
            *(uint2*)&g_pglo[ro + lane*4 + 128*i] = ul;
        }
    }
    uint64_t cwp[8], cwmp[8];
    #pragma unroll
    for (int i = 0; i < 4; i++){
        const float* f = (const float*)&cw4[i];
        const float* m = (const float*)&cwm4[i];
        cwp[2*i]    = pk2(f[0], f[1]);
        cwp[2*i+1]  = pk2(f[2], f[3]);
        cwmp[2*i]   = pk2(m[0], m[1]);
        cwmp[2*i+1] = pk2(m[2], m[3]);
    }
    float sumcw;
    {
        float s = 0.f;
        #pragma unroll
        for (int i = 0; i < 4; i++){
            const float* f = (const float*)&cw4[i];
            s += f[0] + f[1] + f[2] + f[3];
        }
        #pragma unroll
        for (int sh = 16; sh > 0; sh >>= 1) s += __shfl_xor_sync(0xffffffffu, s, sh);
        sumcw = s;
    }

    const uint64_t TWO2 = 0x4000000040000000ull;
    const uint64_t SGN2 = 0x8000000080000000ull;
    const float* cmb = g_cm + (size_t)b*T_*D_ + lane*4;
    for (int tp = 0; tp < T_; tp++){
        const float* cr = cmb + (size_t)tp*D_;
        uint64_t acc2 = 0;
        #pragma unroll
        for (int i = 0; i < 4; i++){
            ulonglong2 cu = __ldg((const ulonglong2*)(cr + 128*i));
            #pragma unroll
            for (int h = 0; h < 2; h++){
                uint64_t x2 = add2(h ? cu.y : cu.x, cwmp[2*i + h]);
                float x0, x1; upk2(x2, x0, x1);
                float den0 = ex2f(x0) + 1.f;
                float den1 = ex2f(x1) + 1.f;
                float sd0 = __uint_as_float(0x7EF311C4u - __float_as_uint(den0));
                float sd1 = __uint_as_float(0x7EF311C4u - __float_as_uint(den1));
                uint64_t nden2 = pk2(den0, den1) ^ SGN2;
                uint64_t r2 = pk2(sd0, sd1);
                r2 = mul2(r2, fma2(nden2, r2, TWO2));
                r2 = mul2(r2, fma2(nden2, r2, TWO2));
                acc2 = fma2(cwp[2*i + h], r2, acc2);
            }
        }
        float aa0, aa1; upk2(acc2, aa0, aa1);
        float acc = aa0 + aa1;
        #pragma unroll
        for (int sh = 16; sh > 0; sh >>= 1) acc += __shfl_xor_sync(0xffffffffu, acc, sh);
        if (lane == 0) s_sc[tp][w] = fmaf(-2.f, acc, sumcw);
    }
    __syncwarp();
    float mx = -1e30f;
    for (int tp = lane; tp < T_; tp += 32) mx = fmaxf(mx, s_sc[tp][w]);
    #pragma unroll
    for (int sh = 16; sh > 0; sh >>= 1) mx = fmaxf(mx, __shfl_xor_sync(0xffffffffu, mx, sh));
    float sum = 0.f;
    for (int tp = lane; tp < T_; tp += 32){
        float e = ex2f((s_sc[tp][w] - mx) * 1.4426950408889634f);
        s_sc[tp][w] = e; sum += e;
    }
    #pragma unroll
    for (int sh = 16; sh > 0; sh >>= 1) sum += __shfl_xor_sync(0xffffffffu, sum, sh);
    if (lane == 0) s_rs[w] = 1.0f / sum;
    __syncthreads();

    const int d0 = tid, d1 = tid + 256;
    uint64_t A0[4], A1[4];
    #pragma unroll
    for (int q = 0; q < 4; q++){ A0[q] = 0; A1[q] = 0; }
    const float* vb = v + (size_t)b*T_*D_;
    for (int tp = 0; tp < T_; tp++){
        float v0 = vb[tp*D_ + d0], v1 = vb[tp*D_ + d1];
        uint64_t v00 = pk2(v0, v0), v11 = pk2(v1, v1);
        const uint64_t* ep = (const uint64_t*)&s_sc[tp][0];
        #pragma unroll
        for (int q = 0; q < 4; q++){
            uint64_t ee = ep[q];
            A0[q] = fma2(v00, ee, A0[q]);
            A1[q] = fma2(v11, ee, A1[q]);
        }
    }
    float a0[8], a1[8];
    #pragma unroll
    for (int q = 0; q < 4; q++){
        upk2(A0[q], a0[2*q], a0[2*q+1]);
        upk2(A1[q], a1[2*q], a1[2*q+1]);
    }
    #pragma unroll
    for (int k = 0; k < 8; k++){
        float rs = s_rs[k];
        size_t ro = (size_t)((t0+k)*B_ + b)*(2*D_) + D_;
        float c0 = a0[k]*rs, c1 = a1[k]*rs;
        __nv_bfloat16 h0 = __float2bfloat16_rn(c0);
        __nv_bfloat16 h1 = __float2bfloat16_rn(c1);
        g_pghi[ro + d0] = h0;
        g_pglo[ro + d0] = __float2bfloat16_rn(c0 - __bfloat162float(h0));
        g_pghi[ro + d1] = h1;
        g_pglo[ro + d1] = __float2bfloat16_rn(c1 - __bfloat162float(h1));
    }
}

// ---------------- persistent GRU scan ----------------
// 128 blocks: dir = bid>>6, kbase = (bid&63)*4. PER-DIR barrier (64 arrivals).
// Split arrive/wait: out-store happens AFTER arrival (doesn't gate peers).
// hnew staged through smem -> coalesced STG.128 for Hbuf and out.
__global__ __launch_bounds__(256)
void scan_kernel(const float* __restrict__ Whh_f, const float* __restrict__ Whh_b,
                 const float* __restrict__ bhh_f, const float* __restrict__ bhh_b,
                 float* __restrict__ out)
{
    extern __shared__ float sm[];
    float* whh_s = sm;                 // [12][256]
    float* h_s   = sm + 12*256;        // [64][260]
    float* hn_s  = sm + 12*256 + 64*260;  // [64][4]
    const int tid = threadIdx.x, bid = blockIdx.x;
    const int dir = bid >> 6, kbase = (bid & 63) << 2;
    const int b = tid & 63, j = tid >> 6;
    const int krow = kbase + j;
    const float* Whh = dir ? Whh_b : Whh_f;
    const float* bhh = dir ? bhh_b : bhh_f;
    const float* gix = dir ? g_gixb : g_gixf;

    for (int idx = tid; idx < 12*256; idx += 256){
        int rr = idx >> 8, col = idx & 255;
        int g = rr >> 2, jj = rr & 3;
        whh_s[idx] = Whh[(size_t)(g*H_ + kbase + jj)*H_ + col];
    }
    const float bh0 = bhh[krow], bh1 = bhh[H_+krow], bh2 = bhh[2*H_+krow];

    __shared__ unsigned s_gen0;
    if (tid == 0) s_gen0 = *(volatile unsigned*)&g_gen2[dir];

    // zero h (buf 0): [dir][b][krow]
    g_Hbuf[((size_t)dir*B_ + b)*H_ + krow] = 0.f;
    __threadfence();
    __syncthreads();
    // initial arrive
    if (tid == 0){
        unsigned tk = atomicAdd(&g_cnt2[dir], 1);
        if (tk == 63){ g_cnt2[dir] = 0; __threadfence(); atomicAdd(&g_gen2[dir], 1); }
    }

    const ulonglong2* w0p = (const ulonglong2*)(whh_s + (0 + j)*256);
    const ulonglong2* w1p = (const ulonglong2*)(whh_s + (4 + j)*256);
    const ulonglong2* w2p = (const ulonglong2*)(whh_s + (8 + j)*256);

    for (int t = 0; t < T_; t++){
        // ---- wait: h(t) visible ----
        if (tid == 0){
            unsigned target = s_gen0 + (unsigned)(t + 1);
            while ((int)(*(volatile unsigned*)&g_gen2[dir] - target) < 0) { }
        }
        __syncthreads();

        const int buf = t & 1;
        const float* hg = g_Hbuf + (size_t)(buf*2 + dir)*B_*H_;
        #pragma unroll
        for (int it = 0; it < 16; it++){
            int idx = it*1024 + tid*4;
            float4 hv = __ldcg((const float4*)(hg + idx));
            int bb = idx >> 8, kk = idx & 255;
            *(float4*)&h_s[bb*260 + kk] = hv;
        }
        const float* gr = gix + ((size_t)t*B_ + b)*(3*H_);
        float gi0 = __ldg(gr + krow);
        float gi1 = __ldg(gr + H_  + krow);
        float gi2 = __ldg(gr + 2*H_ + krow);
        __syncthreads();

        const ulonglong2* hp = (const ulonglong2*)&h_s[b*260];
        uint64_t A0 = 0, A1 = 0, A2 = 0;
        #pragma unroll 4
        for (int kq = 0; kq < 64; kq++){
            ulonglong2 hv = hp[kq];
            ulonglong2 w0v = w0p[kq];
            ulonglong2 w1v = w1p[kq];
            ulonglong2 w2v = w2p[kq];
            A0 = fma2(w0v.x, hv.x, A0); A0 = fma2(w0v.y, hv.y, A0);
            A1 = fma2(w1v.x, hv.x, A1); A1 = fma2(w1v.y, hv.y, A1);
            A2 = fma2(w2v.x, hv.x, A2); A2 = fma2(w2v.y, hv.y, A2);
        }
        float a0x, a0y, a1x, a1y, a2x, a2y;
        upk2(A0, a0x, a0y);
        upk2(A1, a1x, a1y);
        upk2(A2, a2x, a2y);
        float a0 = a0x + a0y, a1 = a1x + a1y, a2 = a2x + a2y;

        float r = sigm(gi0 + a0 + bh0);
        float z = sigm(gi1 + a1 + bh1);
        float n = tanh_acc(gi2 + r*(a2 + bh2));
        float hold = h_s[b*260 + krow];
        float hnew = z*(hold - n) + n;

        // stage hnew -> smem transpose
        hn_s[b*4 + j] = hnew;
        __syncthreads();

        // coalesced Hbuf write (must precede arrival)
        float4 hv4;
        if (tid < 64) hv4 = *(const float4*)&hn_s[tid*4];
        if (tid < 64)
            *(float4*)&g_Hbuf[(size_t)((buf^1)*2 + dir)*B_*H_ + (size_t)tid*H_ + kbase] = hv4;
        __threadfence();
        __syncthreads();

        // ---- arrive (release if last) ----
        if (tid == 0){
            unsigned tk = atomicAdd(&g_cnt2[dir], 1);
            if (tk == 63){ g_cnt2[dir] = 0; __threadfence(); atomicAdd(&g_gen2[dir], 1); }
        }

        // out store AFTER arrival (overlaps peers' arrivals)
        if (tid < 64)
            *(float4*)&out[((size_t)t*B_ + tid)*(2*H_) + dir*H_ + kbase] = hv4;
    }
}

// ---------------- launch ----------------
extern "C" void kernel_launch(void* const* d_in, const int* in_sizes, int n_in,
                              void* d_out, int out_size)
{
    (void)in_sizes; (void)n_in; (void)out_size;
    const float* v     = (const float*)d_in[0];
    const float* W1    = (const float*)d_in[1];
    const float* b1    = (const float*)d_in[2];
    const float* W2    = (const float*)d_in[3];
    const float* b2    = (const float*)d_in[4];
    const float* Wg    = (const float*)d_in[5];
    const float* bg    = (const float*)d_in[6];
    const float* Wih_f = (const float*)d_in[7];
    const float* Whh_f = (const float*)d_in[8];
    const float* bih_f = (const float*)d_in[9];
    const float* bhh_f = (const float*)d_in[10];
    const float* Wih_b = (const float*)d_in[11];
    const float* Whh_b = (const float*)d_in[12];
    const float* bih_b = (const float*)d_in[13];
    const float* bhh_b = (const float*)d_in[14];
    float* out = (float*)d_out;

    cudaFuncSetAttribute(scan_kernel, cudaFuncAttributeMaxDynamicSharedMemorySize, SCAN_SMEM);
    cudaFuncSetAttribute(tgemm_dual_kernel, cudaFuncAttributeMaxDynamicSharedMemorySize, GEMM_DSMEM);
    cudaFuncSetAttribute(tgemm_gate_kernel, cudaFuncAttributeMaxDynamicSharedMemorySize, GEMM_DSMEM);

    void *p_cm, *p_cwm, *p_gxf, *p_gxb;
    void *p_vhi, *p_vlo, *p_pghi, *p_pglo, *p_gihi, *p_gilo;
    void *p_w1hi, *p_w1lo, *p_w2hi, *p_w2lo, *p_wghi, *p_wglo;
    void *p_wfhi, *p_wflo, *p_wbhi, *p_wblo;
    cudaGetSymbolAddress(&p_cm,  g_cm);
    cudaGetSymbolAddress(&p_cwm, g_cwm);
    cudaGetSymbolAddress(&p_gxf, g_gixf);
    cudaGetSymbolAddress(&p_gxb, g_gixb);
    cudaGetSymbolAddress(&p_vhi, g_vhi);   cudaGetSymbolAddress(&p_vlo, g_vlo);
    cudaGetSymbolAddress(&p_pghi, g_pghi); cudaGetSymbolAddress(&p_pglo, g_pglo);
    cudaGetSymbolAddress(&p_gihi, g_gihi); cudaGetSymbolAddress(&p_gilo, g_gilo);
    cudaGetSymbolAddress(&p_w1hi, g_w1hi); cudaGetSymbolAddress(&p_w1lo, g_w1lo);
    cudaGetSymbolAddress(&p_w2hi, g_w2hi); cudaGetSymbolAddress(&p_w2lo, g_w2lo);
    cudaGetSymbolAddress(&p_wghi, g_wghi); cudaGetSymbolAddress(&p_wglo, g_wglo);
    cudaGetSymbolAddress(&p_wfhi, g_wfhi); cudaGetSymbolAddress(&p_wflo, g_wflo);
    cudaGetSymbolAddress(&p_wbhi, g_wbhi); cudaGetSymbolAddress(&p_wblo, g_wblo);

    const int n_v  = (TB*D_)/4;
    const int n_w  = (D_*D_)/4;
    const int n_wg = (2*D_*2*D_)/4;
    const int n_wi = (3*H_*2*D_)/4;
    const int n_tot = n_v + 2*n_w + n_wg + 2*n_wi;
    split6_kernel<<<(n_tot + 255)/256, 256>>>(
        v, W1, W2, Wg, Wih_f, Wih_b,
        (__nv_bfloat16*)p_vhi,  (__nv_bfloat16*)p_vlo,
        (__nv_bfloat16*)p_w1hi, (__nv_bfloat16*)p_w1lo,
        (__nv_bfloat16*)p_w2hi, (__nv_bfloat16*)p_w2lo,
        (__nv_bfloat16*)p_wghi, (__nv_bfloat16*)p_wglo,
        (__nv_bfloat16*)p_wfhi, (__nv_bfloat16*)p_wflo,
        (__nv_bfloat16*)p_wbhi, (__nv_bfloat16*)p_wblo,
        n_v, n_w, n_w, n_wg, n_wi, n_wi);

    #define BF(p) (const __nv_bfloat16*)(p)
    tgemm_dual_kernel<<<dim3((2*D_)/256, TB/128), 256, GEMM_DSMEM>>>(
        BF(p_vhi), BF(p_vlo),
        BF(p_w2hi), BF(p_w2lo), BF(p_w1hi), BF(p_w1lo),
        b2, b1, (float*)p_cm, (float*)p_cwm,
        D_, D_, D_, D_/64, S2E);
    attn_kernel<<<dim3(T_/8, B_), 256>>>(v);
    tgemm_gate_kernel<<<dim3((2*D_)/256, TB/128), 256, GEMM_DSMEM>>>(
        BF(p_pghi), BF(p_pglo), BF(p_wghi), BF(p_wglo), bg,
        (__nv_bfloat16*)p_gihi, (__nv_bfloat16*)p_gilo, 2*D_, 2*D_, (2*D_)/64);
    tgemm_dual_kernel<<<dim3((6*H_)/256, TB/128), 256, GEMM_DSMEM>>>(
        BF(p_gihi), BF(p_gilo),
        BF(p_wfhi), BF(p_wflo), BF(p_wbhi), BF(p_wblo),
        bih_f, bih_b, (float*)p_gxf, (float*)p_gxb,
        3*H_, 3*H_, 2*D_, (2*D_)/64, 1.0f);
    scan_kernel<<<128, 256, SCAN_SMEM>>>(Whh_f, Whh_b, bhh_f, bhh_b, out);
    #undef BF
}

// round 16
// speedup vs baseline: 1.4790x; 1.4790x over previous
#include <cuda_runtime.h>
#include <cuda_bf16.h>
#include <cstdint>

#define B_   64
#define T_   320
#define H_   256
#define D_   512
#define TB   (T_*B_)
#define NBLK 128
#define SCAN_SMEM ((12*256 + 64*260 + 256)*4)
#define BUF_BYTES 98304
#define GEMM_DSMEM (2*BUF_BYTES + 1024)
#define S2E 2.885390081777927f   /* 2*log2(e) */

// ---------------- fp32 scratch ----------------
__device__ float g_cm  [(size_t)TB*D_];
__device__ float g_cwm [(size_t)TB*D_];
__device__ float g_gixf[(size_t)TB*3*H_];
__device__ float g_gixb[(size_t)TB*3*H_];
__device__ float g_Hbuf[2*2*B_*H_];     // [buf][dir][b][k]
__device__ unsigned g_cnt;
__device__ unsigned g_gen;

// ---------------- bf16 hi/lo planes ----------------
__device__ __nv_bfloat16 g_vhi [(size_t)TB*D_],   g_vlo [(size_t)TB*D_];
__device__ __nv_bfloat16 g_pghi[(size_t)TB*2*D_], g_pglo[(size_t)TB*2*D_];
__device__ __nv_bfloat16 g_gihi[(size_t)TB*2*D_], g_gilo[(size_t)TB*2*D_];
__device__ __nv_bfloat16 g_w1hi[D_*D_],     g_w1lo[D_*D_];
__device__ __nv_bfloat16 g_w2hi[D_*D_],     g_w2lo[D_*D_];
__device__ __nv_bfloat16 g_wghi[2*D_*2*D_], g_wglo[2*D_*2*D_];
__device__ __nv_bfloat16 g_wfhi[3*H_*2*D_], g_wflo[3*H_*2*D_];
__device__ __nv_bfloat16 g_wbhi[3*H_*2*D_], g_wblo[3*H_*2*D_];

// ---------------- math ----------------
__device__ __forceinline__ float ex2f(float x){ float r; asm("ex2.approx.f32 %0, %1;" : "=f"(r) : "f"(x)); return r; }
__device__ __forceinline__ float rcpf(float x){ float r; asm("rcp.approx.f32 %0, %1;" : "=f"(r) : "f"(x)); return r; }
__device__ __forceinline__ float tanh_acc(float x){
    x = fminf(15.f, fmaxf(-15.f, x));
    float e = ex2f(x * S2E);
    return (e - 1.f) * rcpf(e + 1.f);
}
__device__ __forceinline__ float sigm(float x){
    x = fminf(30.f, fmaxf(-30.f, x));
    return rcpf(1.f + ex2f(-x * 1.4426950408889634f));
}

// ---------------- packed f32x2 helpers ----------------
__device__ __forceinline__ uint64_t pk2(float a, float b){
    uint64_t r; asm("mov.b64 %0, {%1, %2};" : "=l"(r) : "f"(a), "f"(b)); return r;
}
__device__ __forceinline__ void upk2(uint64_t p, float& a, float& b){
    asm("mov.b64 {%0, %1}, %2;" : "=f"(a), "=f"(b) : "l"(p));
}
__device__ __forceinline__ uint64_t add2(uint64_t a, uint64_t b){
    uint64_t r; asm("add.rn.f32x2 %0, %1, %2;" : "=l"(r) : "l"(a), "l"(b)); return r;
}
__device__ __forceinline__ uint64_t mul2(uint64_t a, uint64_t b){
    uint64_t r; asm("mul.rn.f32x2 %0, %1, %2;" : "=l"(r) : "l"(a), "l"(b)); return r;
}
__device__ __forceinline__ uint64_t fma2(uint64_t a, uint64_t b, uint64_t c){
    uint64_t r; asm("fma.rn.f32x2 %0, %1, %2, %3;" : "=l"(r) : "l"(a), "l"(b), "l"(c)); return r;
}

__device__ __forceinline__ uint32_t smem_u32(const void* p) {
    uint32_t a;
    asm("{ .reg .u64 t; cvta.to.shared.u64 t, %1; cvt.u32.u64 %0, t; }" : "=r"(a) : "l"(p));
    return a;
}
__device__ __forceinline__ uint32_t swz(uint32_t o){ return o ^ ((o >> 3) & 0x70); }

__device__ __forceinline__ void ldm4(uint32_t* r, uint32_t addr){
    asm volatile("ldmatrix.sync.aligned.m8n8.x4.shared.b16 {%0,%1,%2,%3}, [%4];"
        : "=r"(r[0]), "=r"(r[1]), "=r"(r[2]), "=r"(r[3]) : "r"(addr));
}
__device__ __forceinline__ void mma16816(float* c, const uint32_t* a, const uint32_t* b){
    asm volatile("mma.sync.aligned.m16n8k16.row.col.f32.bf16.bf16.f32 "
        "{%0,%1,%2,%3}, {%4,%5,%6,%7}, {%8,%9}, {%0,%1,%2,%3};"
        : "+f"(c[0]), "+f"(c[1]), "+f"(c[2]), "+f"(c[3])
        : "r"(a[0]), "r"(a[1]), "r"(a[2]), "r"(a[3]), "r"(b[0]), "r"(b[1]));
}
__device__ __forceinline__ void cpa16(uint32_t dst, const void* src){
    asm volatile("cp.async.cg.shared.global [%0], [%1], 16;" :: "r"(dst), "l"(src));
}
#define CP_COMMIT() asm volatile("cp.async.commit_group;" ::: "memory")
#define CP_WAIT1()  asm volatile("cp.async.wait_group 1;" ::: "memory")
#define CP_WAIT0()  asm volatile("cp.async.wait_group 0;" ::: "memory")

// ---------------- merged fp32 -> (hi, lo) bf16 split ----------------
__device__ __forceinline__ void split_one(const float* in, __nv_bfloat16* hi,
                                          __nv_bfloat16* lo, int i)
{
    float4 f = ((const float4*)in)[i];
    __nv_bfloat16 hx = __float2bfloat16_rn(f.x), hy = __float2bfloat16_rn(f.y);
    __nv_bfloat16 hz = __float2bfloat16_rn(f.z), hw = __float2bfloat16_rn(f.w);
    __nv_bfloat162 p0, p1; uint2 u;
    p0.x = hx; p0.y = hy; p1.x = hz; p1.y = hw;
    u.x = *(uint32_t*)&p0; u.y = *(uint32_t*)&p1;
    ((uint2*)hi)[i] = u;
    p0.x = __float2bfloat16_rn(f.x - __bfloat162float(hx));
    p0.y = __float2bfloat16_rn(f.y - __bfloat162float(hy));
    p1.x = __float2bfloat16_rn(f.z - __bfloat162float(hz));
    p1.y = __float2bfloat16_rn(f.w - __bfloat162float(hw));
    u.x = *(uint32_t*)&p0; u.y = *(uint32_t*)&p1;
    ((uint2*)lo)[i] = u;
}

__global__ void split6_kernel(
    const float* s0, const float* s1, const float* s2,
    const float* s3, const float* s4, const float* s5,
    __nv_bfloat16* h0, __nv_bfloat16* l0, __nv_bfloat16* h1, __nv_bfloat16* l1,
    __nv_bfloat16* h2, __nv_bfloat16* l2, __nv_bfloat16* h3, __nv_bfloat16* l3,
    __nv_bfloat16* h4, __nv_bfloat16* l4, __nv_bfloat16* h5, __nv_bfloat16* l5,
    int n0, int n1, int n2, int n3, int n4, int n5)
{
    int j = blockIdx.x * blockDim.x + threadIdx.x;
    if (j < n0){ split_one(s0, h0, l0, j); return; } j -= n0;
    if (j < n1){ split_one(s1, h1, l1, j); return; } j -= n1;
    if (j < n2){ split_one(s2, h2, l2, j); return; } j -= n2;
    if (j < n3){ split_one(s3, h3, l3, j); return; } j -= n3;
    if (j < n4){ split_one(s4, h4, l4, j); return; } j -= n4;
    if (j < n5){ split_one(s5, h5, l5, j); }
}

// ======== GEMM core ========
struct GemmCore {
    template<typename FA>
    __device__ __forceinline__ static void run(
        float (&acc)[4][8][4],
        const __nv_bfloat16* Ahi, const __nv_bfloat16* Alo,
        const __nv_bfloat16* Bhi, const __nv_bfloat16* Blo,
        int bm, int bnl, int K, int Ktiles,
        uint32_t tbase, int tid)
    {
        const int wid = tid >> 5, lane = tid & 31;
        const int wm = (wid & 1) * 64, wn = (wid >> 1) * 64;
        const uint32_t aoff0 = (uint32_t)(wm + (lane & 15)) * 128 + ((lane >> 4) << 4);
        const uint32_t boff0 = (uint32_t)(wn + (lane & 7) + ((lane >> 4) << 3)) * 128 + (((lane >> 3) & 1) << 4);

        auto issue = [&](int kt, int buf){
            const uint32_t bb = tbase + (uint32_t)buf * BUF_BYTES;
            const int kof = kt * 64;
            #pragma unroll
            for (int i = 0; i < 8; i++){
                int idx = tid + 256*i;
                int plane = idx >> 10, rem = idx & 1023, row = rem >> 3, ch = rem & 7;
                const __nv_bfloat16* src = (plane ? Alo : Ahi) + (size_t)(bm + row) * K + kof + ch*8;
                cpa16(bb + plane*16384u + swz((uint32_t)row*128 + ch*16), src);
            }
            #pragma unroll
            for (int i = 0; i < 16; i++){
                int idx = tid + 256*i;
                int plane = idx >> 11, rem = idx & 2047, row = rem >> 3, ch = rem & 7;
                const __nv_bfloat16* src = (plane ? Blo : Bhi) + (size_t)(bnl + row) * K + kof + ch*8;
                cpa16(bb + 32768u + plane*32768u + swz((uint32_t)row*128 + ch*16), src);
            }
        };

        issue(0, 0); CP_COMMIT();
        if (Ktiles > 1){ issue(1, 1); CP_COMMIT(); }

        for (int kt = 0; kt < Ktiles; kt++){
            if (kt + 1 < Ktiles) CP_WAIT1(); else CP_WAIT0();
            __syncthreads();

            const uint32_t ub = tbase + (uint32_t)(kt & 1) * BUF_BYTES;
            const uint32_t uAhi = ub, uAlo = ub + 16384, uBhi = ub + 32768, uBlo = ub + 65536;

            #pragma unroll
            for (int kk = 0; kk < 4; kk++){
                const uint32_t kb = kk * 32;
                uint32_t ah[4][4], al[4][4], bh[4][4], bl[4][4];
                #pragma unroll
                for (int mf = 0; mf < 4; mf++){
                    uint32_t off = swz(aoff0 + (uint32_t)mf*2048 + kb);
                    ldm4(ah[mf], uAhi + off);
                    ldm4(al[mf], uAlo + off);
                }
                #pragma unroll
                for (int nf2 = 0; nf2 < 4; nf2++){
                    uint32_t off = swz(boff0 + (uint32_t)nf2*2048 + kb);
                    ldm4(bh[nf2], uBhi + off);
                    ldm4(bl[nf2], uBlo + off);
                }
                #pragma unroll
                for (int pass = 0; pass < 3; pass++){
                    #pragma unroll
                    for (int mf = 0; mf < 4; mf++){
                        #pragma unroll
                        for (int nf = 0; nf < 8; nf++){
                            const uint32_t* ap = (pass == 2) ? al[mf] : ah[mf];
                            const uint32_t* bp = (pass == 1) ? &bl[nf >> 1][(nf & 1) * 2]
                                                             : &bh[nf >> 1][(nf & 1) * 2];
                            mma16816(acc[mf][nf], ap, bp);
                        }
                    }
                }
            }
            if (kt + 2 < Ktiles){
                __syncthreads();
                issue(kt + 2, kt & 1);
                CP_COMMIT();
            }
        }
    }
};

// ---------------- dual-output GEMM ----------------
__global__ __launch_bounds__(256, 1)
void tgemm_dual_kernel(const __nv_bfloat16* __restrict__ Ahi, const __nv_bfloat16* __restrict__ Alo,
                       const __nv_bfloat16* __restrict__ B1hi, const __nv_bfloat16* __restrict__ B1lo,
                       const __nv_bfloat16* __restrict__ B2hi, const __nv_bfloat16* __restrict__ B2lo,
                       const float* __restrict__ bias1, const float* __restrict__ bias2,
                       float* __restrict__ C1, float* __restrict__ C2,
                       int N1, int N2, int K, int Ktiles, float scl)
{
    extern __shared__ char dsm[];
    const int tid = threadIdx.x, wid = tid >> 5, lane = tid & 31;
    const int bm = blockIdx.y * 128, bn = blockIdx.x * 256;
    const int wm = (wid & 1) * 64, wn = (wid >> 1) * 64;
    uint32_t sbase = smem_u32(dsm);
    uint32_t tbase = (sbase + 1023u) & ~1023u;

    const bool second = (bn >= N1);
    const int bnl = second ? bn - N1 : bn;
    const __nv_bfloat16* Bhi = second ? B2hi : B1hi;
    const __nv_bfloat16* Blo = second ? B2lo : B1lo;
    const float* bias = second ? bias2 : bias1;
    float* C = second ? C2 : C1;
    const int Nout = second ? N2 : N1;

    float acc[4][8][4];
    #pragma unroll
    for (int i = 0; i < 4; i++)
        #pragma unroll
        for (int j = 0; j < 8; j++)
            #pragma unroll
            for (int q = 0; q < 4; q++) acc[i][j][q] = 0.f;

    GemmCore::run<int>(acc, Ahi, Alo, Bhi, Blo, bm, bnl, K, Ktiles, tbase, tid);

    #pragma unroll
    for (int mf = 0; mf < 4; mf++){
        const int row = bm + wm + mf*16 + (lane >> 2);
        #pragma unroll
        for (int nf = 0; nf < 8; nf++){
            const int col = bnl + wn + nf*8 + (lane & 3)*2;
            float2 bs = *(const float2*)&bias[col];
            float2 o0, o1;
            o0.x = (acc[mf][nf][0] + bs.x) * scl;  o0.y = (acc[mf][nf][1] + bs.y) * scl;
            o1.x = (acc[mf][nf][2] + bs.x) * scl;  o1.y = (acc[mf][nf][3] + bs.y) * scl;
            *(float2*)&C[(size_t)row * Nout + col]     = o0;
            *(float2*)&C[(size_t)(row+8) * Nout + col] = o1;
        }
    }
}

// ---------------- gate GEMM ----------------
__global__ __launch_bounds__(256, 1)
void tgemm_gate_kernel(const __nv_bfloat16* __restrict__ Ahi, const __nv_bfloat16* __restrict__ Alo,
                       const __nv_bfloat16* __restrict__ Bhi, const __nv_bfloat16* __restrict__ Blo,
                       const float* __restrict__ bias,
                       __nv_bfloat16* __restrict__ Chi, __nv_bfloat16* __restrict__ Clo,
                       int N, int K, int Ktiles)
{
    extern __shared__ char dsm[];
    const int tid = threadIdx.x, wid = tid >> 5, lane = tid & 31;
    const int bm = blockIdx.y * 128, bn = blockIdx.x * 256;
    const int wm = (wid & 1) * 64, wn = (wid >> 1) * 64;
    uint32_t sbase = smem_u32(dsm);
    uint32_t tbase = (sbase + 1023u) & ~1023u;

    float acc[4][8][4];
    #pragma unroll
    for (int i = 0; i < 4; i++)
        #pragma unroll
        for (int j = 0; j < 8; j++)
            #pragma unroll
            for (int q = 0; q < 4; q++) acc[i][j][q] = 0.f;

    GemmCore::run<int>(acc, Ahi, Alo, Bhi, Blo, bm, bn, K, Ktiles, tbase, tid);

    #pragma unroll
    for (int mf = 0; mf < 4; mf++){
        const int row = bm + wm + mf*16 + (lane >> 2);
        #pragma unroll
        for (int nf = 0; nf < 8; nf++){
            const int col = bn + wn + nf*8 + (lane & 3)*2;
            float2 bs = *(const float2*)&bias[col];
            float2 o0, o1;
            o0.x = acc[mf][nf][0] + bs.x;  o0.y = acc[mf][nf][1] + bs.y;
            o1.x = acc[mf][nf][2] + bs.x;  o1.y = acc[mf][nf][3] + bs.y;
            __nv_bfloat162 h0 = *(const __nv_bfloat162*)&Ahi[(size_t)row*K + col];
            __nv_bfloat162 l0 = *(const __nv_bfloat162*)&Alo[(size_t)row*K + col];
            __nv_bfloat162 h1 = *(const __nv_bfloat162*)&Ahi[(size_t)(row+8)*K + col];
            __nv_bfloat162 l1 = *(const __nv_bfloat162*)&Alo[(size_t)(row+8)*K + col];
            float g0x = (__bfloat162float(h0.x)+__bfloat162float(l0.x)) * sigm(o0.x);
            float g0y = (__bfloat162float(h0.y)+__bfloat162float(l0.y)) * sigm(o0.y);
            float g1x = (__bfloat162float(h1.x)+__bfloat162float(l1.x)) * sigm(o1.x);
            float g1y = (__bfloat162float(h1.y)+__bfloat162float(l1.y)) * sigm(o1.y);
            __nv_bfloat162 oh, ol;
            oh.x = __float2bfloat16_rn(g0x); oh.y = __float2bfloat16_rn(g0y);
            ol.x = __float2bfloat16_rn(g0x - __bfloat162float(oh.x));
            ol.y = __float2bfloat16_rn(g0y - __bfloat162float(oh.y));
            *(__nv_bfloat162*)&Chi[(size_t)row*N + col] = oh;
            *(__nv_bfloat162*)&Clo[(size_t)row*N + col] = ol;
            oh.x = __float2bfloat16_rn(g1x); oh.y = __float2bfloat16_rn(g1y);
            ol.x = __float2bfloat16_rn(g1x - __bfloat162float(oh.x));
            ol.y = __float2bfloat16_rn(g1y - __bfloat162float(oh.y));
            *(__nv_bfloat162*)&Chi[(size_t)(row+8)*N + col] = oh;
            *(__nv_bfloat162*)&Clo[(size_t)(row+8)*N + col] = ol;
        }
    }
}

// ---------------- fused attention ----------------
__global__ __launch_bounds__(256)
void attn_kernel(const float* __restrict__ v)
{
    __shared__ float s_sc[T_][10];
    __shared__ float s_rs[8];
    const int b = blockIdx.y;
    const int t0 = blockIdx.x << 3;
    const int tid = threadIdx.x, w = tid >> 5, lane = tid & 31;
    const int t = t0 + w;

    const float* vrow = v     + ((size_t)b*T_ + t)*D_;
    const float* mrow = g_cwm + ((size_t)b*T_ + t)*D_;
    float4 cw4[4], cwm4[4];
    #pragma unroll
    for (int i = 0; i < 4; i++){
        cw4[i]  = __ldg((const float4*)(vrow + lane*4 + 128*i));
        cwm4[i] = __ldg((const float4*)(mrow + lane*4 + 128*i));
    }
    {
        size_t ro = (size_t)(t*B_ + b)*(2*D_);
        #pragma unroll
        for (int i = 0; i < 4; i++){
            const float* f = (const float*)&cw4[i];
            __nv_bfloat162 ph0, ph1, pl0, pl1;
            ph0.x = __float2bfloat16_rn(f[0]); ph0.y = __float2bfloat16_rn(f[1]);
            ph1.x = __float2bfloat16_rn(f[2]); ph1.y = __float2bfloat16_rn(f[3]);
            pl0.x = __float2bfloat16_rn(f[0] - __bfloat162float(ph0.x));
            pl0.y = __float2bfloat16_rn(f[1] - __bfloat162float(ph0.y));
            pl1.x = __float2bfloat16_rn(f[2] - __bfloat162float(ph1.x));
            pl1.y = __float2bfloat16_rn(f[3] - __bfloat162float(ph1.y));
            uint2 uh, ul;
            uh.x = *(uint32_t*)&ph0; uh.y = *(uint32_t*)&ph1;
            ul.x = *(uint32_t*)&pl0; ul.y = *(uint32_t*)&pl1;
            *(uint2*)&g_pghi[ro + lane*4 + 128*i] = uh;
            *(uint2*)&g_pglo[ro + lane*4 + 128*i] = ul;
        }
    }
    uint64_t cwp[8], cwmp[8];
    #pragma unroll
    for (int i = 0; i < 4; i++){
        const float* f = (const float*)&cw4[i];
        const float* m = (const float*)&cwm4[i];
        cwp[2*i]    = pk2(f[0], f[1]);
        cwp[2*i+1]  = pk2(f[2], f[3]);
        cwmp[2*i]   = pk2(m[0], m[1]);
        cwmp[2*i+1] = pk2(m[2], m[3]);
    }
    float sumcw;
    {
        float s = 0.f;
        #pragma unroll
        for (int i = 0; i < 4; i++){
            const float* f = (const float*)&cw4[i];
            s += f[0] + f[1] + f[2] + f[3];
        }
        #pragma unroll
        for (int sh = 16; sh > 0; sh >>= 1) s += __shfl_xor_sync(0xffffffffu, s, sh);
        sumcw = s;
    }

    const uint64_t TWO2 = 0x4000000040000000ull;
    const uint64_t SGN2 = 0x8000000080000000ull;
    const float* cmb = g_cm + (size_t)b*T_*D_ + lane*4;
    for (int tp = 0; tp < T_; tp++){
        const float* cr = cmb + (size_t)tp*D_;
        uint64_t acc2 = 0;
        #pragma unroll
        for (int i = 0; i < 4; i++){
            ulonglong2 cu = __ldg((const ulonglong2*)(cr + 128*i));
            #pragma unroll
            for (int h = 0; h < 2; h++){
                uint64_t x2 = add2(h ? cu.y : cu.x, cwmp[2*i + h]);
                float x0, x1; upk2(x2, x0, x1);
                float den0 = ex2f(x0) + 1.f;
                float den1 = ex2f(x1) + 1.f;
                float sd0 = __uint_as_float(0x7EF311C4u - __float_as_uint(den0));
                float sd1 = __uint_as_float(0x7EF311C4u - __float_as_uint(den1));
                uint64_t nden2 = pk2(den0, den1) ^ SGN2;
                uint64_t r2 = pk2(sd0, sd1);
                r2 = mul2(r2, fma2(nden2, r2, TWO2));
                r2 = mul2(r2, fma2(nden2, r2, TWO2));
                acc2 = fma2(cwp[2*i + h], r2, acc2);
            }
        }
        float aa0, aa1; upk2(acc2, aa0, aa1);
        float acc = aa0 + aa1;
        #pragma unroll
        for (int sh = 16; sh > 0; sh >>= 1) acc += __shfl_xor_sync(0xffffffffu, acc, sh);
        if (lane == 0) s_sc[tp][w] = fmaf(-2.f, acc, sumcw);
    }
    __syncwarp();
    float mx = -1e30f;
    for (int tp = lane; tp < T_; tp += 32) mx = fmaxf(mx, s_sc[tp][w]);
    #pragma unroll
    for (int sh = 16; sh > 0; sh >>= 1) mx = fmaxf(mx, __shfl_xor_sync(0xffffffffu, mx, sh));
    float sum = 0.f;
    for (int tp = lane; tp < T_; tp += 32){
        float e = ex2f((s_sc[tp][w] - mx) * 1.4426950408889634f);
        s_sc[tp][w] = e; sum += e;
    }
    #pragma unroll
    for (int sh = 16; sh > 0; sh >>= 1) sum += __shfl_xor_sync(0xffffffffu, sum, sh);
    if (lane == 0) s_rs[w] = 1.0f / sum;
    __syncthreads();

    const int d0 = tid, d1 = tid + 256;
    uint64_t A0[4], A1[4];
    #pragma unroll
    for (int q = 0; q < 4; q++){ A0[q] = 0; A1[q] = 0; }
    const float* vb = v + (size_t)b*T_*D_;
    for (int tp = 0; tp < T_; tp++){
        float v0 = vb[tp*D_ + d0], v1 = vb[tp*D_ + d1];
        uint64_t v00 = pk2(v0, v0), v11 = pk2(v1, v1);
        const uint64_t* ep = (const uint64_t*)&s_sc[tp][0];
        #pragma unroll
        for (int q = 0; q < 4; q++){
            uint64_t ee = ep[q];
            A0[q] = fma2(v00, ee, A0[q]);
            A1[q] = fma2(v11, ee, A1[q]);
        }
    }
    float a0[8], a1[8];
    #pragma unroll
    for (int q = 0; q < 4; q++){
        upk2(A0[q], a0[2*q], a0[2*q+1]);
        upk2(A1[q], a1[2*q], a1[2*q+1]);
    }
    #pragma unroll
    for (int k = 0; k < 8; k++){
        float rs = s_rs[k];
        size_t ro = (size_t)((t0+k)*B_ + b)*(2*D_) + D_;
        float c0 = a0[k]*rs, c1 = a1[k]*rs;
        __nv_bfloat16 h0 = __float2bfloat16_rn(c0);
        __nv_bfloat16 h1 = __float2bfloat16_rn(c1);
        g_pghi[ro + d0] = h0;
        g_pglo[ro + d0] = __float2bfloat16_rn(c0 - __bfloat162float(h0));
        g_pghi[ro + d1] = h1;
        g_pglo[ro + d1] = __float2bfloat16_rn(c1 - __bfloat162float(h1));
    }
}

// ---------------- persistent GRU scan (R13 barrier + coalesced stores) ------
__device__ __forceinline__ void grid_barrier(unsigned expect){
    __threadfence();
    __syncthreads();
    if (threadIdx.x == 0){
        unsigned t = atomicAdd(&g_cnt, 1);
        if (t == NBLK-1){
            g_cnt = 0;
            __threadfence();
            atomicAdd(&g_gen, 1);
        } else {
            while ((int)(*(volatile unsigned*)&g_gen - expect) < 0) { }
        }
    }
    __syncthreads();
}

// global h: [buf][dir][b][k]; smem h_s: [b][k] stride 260; hn_s staging [64][4].
__global__ __launch_bounds__(256)
void scan_kernel(const float* __restrict__ Whh_f, const float* __restrict__ Whh_b,
                 const float* __restrict__ bhh_f, const float* __restrict__ bhh_b,
                 float* __restrict__ out)
{
    extern __shared__ float sm[];
    float* whh_s = sm;                    // [12][256]
    float* h_s   = sm + 12*256;           // [64][260]
    float* hn_s  = sm + 12*256 + 64*260;  // [64][4]
    const int tid = threadIdx.x, bid = blockIdx.x;
    const int dir = bid >> 6, kbase = (bid & 63) << 2;
    const int b = tid & 63, j = tid >> 6;
    const int krow = kbase + j;
    const float* Whh = dir ? Whh_b : Whh_f;
    const float* bhh = dir ? bhh_b : bhh_f;
    const float* gix = dir ? g_gixb : g_gixf;

    for (int idx = tid; idx < 12*256; idx += 256){
        int rr = idx >> 8, col = idx & 255;
        int g = rr >> 2, jj = rr & 3;
        whh_s[idx] = Whh[(size_t)(g*H_ + kbase + jj)*H_ + col];
    }
    const float bh0 = bhh[krow], bh1 = bhh[H_+krow], bh2 = bhh[2*H_+krow];

    __shared__ unsigned s_gen0;
    if (tid == 0) s_gen0 = *(volatile unsigned*)&g_gen;

    // zero h (buf 0): [dir][b][krow]
    g_Hbuf[((size_t)dir*B_ + b)*H_ + krow] = 0.f;
    __syncthreads();
    unsigned nb = 0;
    grid_barrier(s_gen0 + (++nb));

    const ulonglong2* w0p = (const ulonglong2*)(whh_s + (0 + j)*256);
    const ulonglong2* w1p = (const ulonglong2*)(whh_s + (4 + j)*256);
    const ulonglong2* w2p = (const ulonglong2*)(whh_s + (8 + j)*256);

    for (int t = 0; t < T_; t++){
        const int buf = t & 1;
        const float* hg = g_Hbuf + (size_t)(buf*2 + dir)*B_*H_;
        #pragma unroll
        for (int it = 0; it < 16; it++){
            int idx = it*1024 + tid*4;
            float4 hv = __ldcg((const float4*)(hg + idx));
            int bb = idx >> 8, kk = idx & 255;
            *(float4*)&h_s[bb*260 + kk] = hv;
        }
        const float* gr = gix + ((size_t)t*B_ + b)*(3*H_);
        float gi0 = __ldg(gr + krow);
        float gi1 = __ldg(gr + H_  + krow);
        float gi2 = __ldg(gr + 2*H_ + krow);
        __syncthreads();

        const ulonglong2* hp = (const ulonglong2*)&h_s[b*260];
        uint64_t A0 = 0, A1 = 0, A2 = 0;
        #pragma unroll 4
        for (int kq = 0; kq < 64; kq++){
            ulonglong2 hv = hp[kq];
            ulonglong2 w0v = w0p[kq];
            ulonglong2 w1v = w1p[kq];
            ulonglong2 w2v = w2p[kq];
            A0 = fma2(w0v.x, hv.x, A0); A0 = fma2(w0v.y, hv.y, A0);
            A1 = fma2(w1v.x, hv.x, A1); A1 = fma2(w1v.y, hv.y, A1);
            A2 = fma2(w2v.x, hv.x, A2); A2 = fma2(w2v.y, hv.y, A2);
        }
        float a0x, a0y, a1x, a1y, a2x, a2y;
        upk2(A0, a0x, a0y);
        upk2(A1, a1x, a1y);
        upk2(A2, a2x, a2y);
        float a0 = a0x + a0y, a1 = a1x + a1y, a2 = a2x + a2y;

        float r = sigm(gi0 + a0 + bh0);
        float z = sigm(gi1 + a1 + bh1);
        float n = tanh_acc(gi2 + r*(a2 + bh2));
        float hold = h_s[b*260 + krow];
        float hnew = z*(hold - n) + n;

        // stage hnew through smem, then coalesced STG.128 for Hbuf + out
        hn_s[b*4 + j] = hnew;
        __syncthreads();
        if (tid < 64){
            float4 hv4 = *(const float4*)&hn_s[tid*4];
            *(float4*)&g_Hbuf[(size_t)((buf^1)*2 + dir)*B_*H_ + (size_t)tid*H_ + kbase] = hv4;
            *(float4*)&out[((size_t)t*B_ + tid)*(2*H_) + dir*H_ + kbase] = hv4;
        }

        grid_barrier(s_gen0 + (++nb));
    }
}

// ---------------- launch ----------------
extern "C" void kernel_launch(void* const* d_in, const int* in_sizes, int n_in,
                              void* d_out, int out_size)
{
    (void)in_sizes; (void)n_in; (void)out_size;
    const float* v     = (const float*)d_in[0];
    const float* W1    = (const float*)d_in[1];
    const float* b1    = (const float*)d_in[2];
    const float* W2    = (const float*)d_in[3];
    const float* b2    = (const float*)d_in[4];
    const float* Wg    = (const float*)d_in[5];
    const float* bg    = (const float*)d_in[6];
    const float* Wih_f = (const float*)d_in[7];
    const float* Whh_f = (const float*)d_in[8];
    const float* bih_f = (const float*)d_in[9];
    const float* bhh_f = (const float*)d_in[10];
    const float* Wih_b = (const float*)d_in[11];
    const float* Whh_b = (const float*)d_in[12];
    const float* bih_b = (const float*)d_in[13];
    const float* bhh_b = (const float*)d_in[14];
    float* out = (float*)d_out;

    cudaFuncSetAttribute(scan_kernel, cudaFuncAttributeMaxDynamicSharedMemorySize, SCAN_SMEM);
    cudaFuncSetAttribute(tgemm_dual_kernel, cudaFuncAttributeMaxDynamicSharedMemorySize, GEMM_DSMEM);
    cudaFuncSetAttribute(tgemm_gate_kernel, cudaFuncAttributeMaxDynamicSharedMemorySize, GEMM_DSMEM);

    void *p_cm, *p_cwm, *p_gxf, *p_gxb;
    void *p_vhi, *p_vlo, *p_pghi, *p_pglo, *p_gihi, *p_gilo;
    void *p_w1hi, *p_w1lo, *p_w2hi, *p_w2lo, *p_wghi, *p_wglo;
    void *p_wfhi, *p_wflo, *p_wbhi, *p_wblo;
    cudaGetSymbolAddress(&p_cm,  g_cm);
    cudaGetSymbolAddress(&p_cwm, g_cwm);
    cudaGetSymbolAddress(&p_gxf, g_gixf);
    cudaGetSymbolAddress(&p_gxb, g_gixb);
    cudaGetSymbolAddress(&p_vhi, g_vhi);   cudaGetSymbolAddress(&p_vlo, g_vlo);
    cudaGetSymbolAddress(&p_pghi, g_pghi); cudaGetSymbolAddress(&p_pglo, g_pglo);
    cudaGetSymbolAddress(&p_gihi, g_gihi); cudaGetSymbolAddress(&p_gilo, g_gilo);
    cudaGetSymbolAddress(&p_w1hi, g_w1hi); cudaGetSymbolAddress(&p_w1lo, g_w1lo);
    cudaGetSymbolAddress(&p_w2hi, g_w2hi); cudaGetSymbolAddress(&p_w2lo, g_w2lo);
    cudaGetSymbolAddress(&p_wghi, g_wghi); cudaGetSymbolAddress(&p_wglo, g_wglo);
    cudaGetSymbolAddress(&p_wfhi, g_wfhi); cudaGetSymbolAddress(&p_wflo, g_wflo);
    cudaGetSymbolAddress(&p_wbhi, g_wbhi); cudaGetSymbolAddress(&p_wblo, g_wblo);

    const int n_v  = (TB*D_)/4;
    const int n_w  = (D_*D_)/4;
    const int n_wg = (2*D_*2*D_)/4;
    const int n_wi = (3*H_*2*D_)/4;
    const int n_tot = n_v + 2*n_w + n_wg + 2*n_wi;
    split6_kernel<<<(n_tot + 255)/256, 256>>>(
        v, W1, W2, Wg, Wih_f, Wih_b,
        (__nv_bfloat16*)p_vhi,  (__nv_bfloat16*)p_vlo,
        (__nv_bfloat16*)p_w1hi, (__nv_bfloat16*)p_w1lo,
        (__nv_bfloat16*)p_w2hi, (__nv_bfloat16*)p_w2lo,
        (__nv_bfloat16*)p_wghi, (__nv_bfloat16*)p_wglo,
        (__nv_bfloat16*)p_wfhi, (__nv_bfloat16*)p_wflo,
        (__nv_bfloat16*)p_wbhi, (__nv_bfloat16*)p_wblo,
        n_v, n_w, n_w, n_wg, n_wi, n_wi);

    #define BF(p) (const __nv_bfloat16*)(p)
    tgemm_dual_kernel<<<dim3((2*D_)/256, TB/128), 256, GEMM_DSMEM>>>(
        BF(p_vhi), BF(p_vlo),
        BF(p_w2hi), BF(p_w2lo), BF(p_w1hi), BF(p_w1lo),
        b2, b1, (float*)p_cm, (float*)p_cwm,
        D_, D_, D_, D_/64, S2E);
    attn_kernel<<<dim3(T_/8, B_), 256>>>(v);
    tgemm_gate_kernel<<<dim3((2*D_)/256, TB/128), 256, GEMM_DSMEM>>>(
        BF(p_pghi), BF(p_pglo), BF(p_wghi), BF(p_wglo), bg,
        (__nv_bfloat16*)p_gihi, (__nv_bfloat16*)p_gilo, 2*D_, 2*D_, (2*D_)/64);
    tgemm_dual_kernel<<<dim3((6*H_)/256, TB/128), 256, GEMM_DSMEM>>>(
        BF(p_gihi), BF(p_gilo),
        BF(p_wfhi), BF(p_wflo), BF(p_wbhi), BF(p_wblo),
        bih_f, bih_b, (float*)p_gxf, (float*)p_gxb,
        3*H_, 3*H_, 2*D_, (2*D_)/64, 1.0f);
    scan_kernel<<<NBLK, 256, SCAN_SMEM>>>(Whh_f, Whh_b, bhh_f, bhh_b, out);
    #undef BF
}